// round 1
// baseline (speedup 1.0000x reference)
#include <cuda_runtime.h>

#define S_SRC 16384
#define T_GRID 4096
#define NHBR 8
#define BATCH 4
#define EDIM 16
#define NTGT 8192

// Scratch (static device globals — no allocation)
__device__ int   g_idx[T_GRID * NHBR];
__device__ float g_w[T_GRID * NHBR];
__device__ float g_xg[BATCH * T_GRID * EDIM];

// ---------------------------------------------------------------------------
// Kernel 1: exact top-8 nearest sources per grid point (warp per point).
// Key = (float_bits(d2) << 32) | src_idx  -> ascending order == (d2 asc, idx asc)
// which reproduces jax.lax.top_k(-d2) ordering incl. tie-break.
// ---------------------------------------------------------------------------
__global__ __launch_bounds__(256) void topk_kernel(
    const float* __restrict__ cs, const float* __restrict__ cg) {
  __shared__ float2 s_src[4096];
  const int warp = threadIdx.x >> 5;
  const int lane = threadIdx.x & 31;
  const int t = (blockIdx.x << 3) + warp;
  const float gx = cg[t];
  const float gy = cg[T_GRID + t];

  unsigned long long best[8];
#pragma unroll
  for (int i = 0; i < 8; i++) best[i] = 0x7F800000FFFFFFFFULL;  // (+inf, max idx)
  float worst = __int_as_float(0x7F800000);                      // +inf

  for (int tile = 0; tile < 4; tile++) {
    const int base = tile * 4096;
    __syncthreads();
    for (int j = threadIdx.x; j < 4096; j += 256) {
      s_src[j] = make_float2(cs[base + j], cs[S_SRC + base + j]);
    }
    __syncthreads();
#pragma unroll 4
    for (int j = lane; j < 4096; j += 32) {
      float2 s = s_src[j];
      float dx = gx - s.x;
      float dy = gy - s.y;
      float d2 = fmaf(dy, dy, dx * dx);
      if (d2 <= worst) {
        unsigned long long key =
            ((unsigned long long)__float_as_uint(d2) << 32) | (unsigned)(base + j);
        if (key < best[7]) {
          best[7] = key;
#pragma unroll
          for (int k = 7; k > 0; k--) {
            unsigned long long lo = (best[k] < best[k - 1]) ? best[k] : best[k - 1];
            unsigned long long hi = (best[k] < best[k - 1]) ? best[k - 1] : best[k];
            best[k - 1] = lo;
            best[k] = hi;
          }
          worst = __uint_as_float((unsigned)(best[7] >> 32));
        }
      }
    }
  }

  // Warp merge: 8 rounds of min-extraction over 32 sorted lists of 8.
  unsigned long long cand = best[0];
  int p = 0;
  unsigned long long mine = 0;
#pragma unroll
  for (int k = 0; k < 8; k++) {
    unsigned long long m = cand;
#pragma unroll
    for (int off = 16; off > 0; off >>= 1) {
      unsigned long long o = __shfl_xor_sync(0xffffffffu, m, off);
      m = (o < m) ? o : m;
    }
    if (lane == k) mine = m;
    if (cand == m) {  // unique owner (keys are unique per source idx)
      p++;
      cand = (p < 8) ? best[p] : 0xFFFFFFFFFFFFFFFFULL;
    }
  }
  if (lane < 8) g_idx[t * NHBR + lane] = (int)(mine & 0xFFFFFFFFu);
}

// ---------------------------------------------------------------------------
// Kernel 2: positional-encoding MLP (gelu-tanh) -> layernorm -> logits -> softmax
// One thread per (t, n). Block = 256 threads = 32 grid points.
// ---------------------------------------------------------------------------
__device__ __forceinline__ void fma4(float4& a, float w, const float4 v) {
  a.x = fmaf(w, v.x, a.x);
  a.y = fmaf(w, v.y, a.y);
  a.z = fmaf(w, v.z, a.z);
  a.w = fmaf(w, v.w, a.w);
}

__global__ __launch_bounds__(256) void weights_kernel(
    const float* __restrict__ cs, const float* __restrict__ cg,
    const float* __restrict__ w1, const float* __restrict__ b1,
    const float* __restrict__ w2, const float* __restrict__ b2,
    const float* __restrict__ lng, const float* __restrict__ lnb,
    const float* __restrict__ kw, const float* __restrict__ kb) {
  __shared__ float sW1[128];       // [2][64]
  __shared__ float sB1[64];
  __shared__ float4 sW2[512];      // [64][32] as float4
  __shared__ float sB2[32], sLNG[32], sLNB[32], sKB[8];
  __shared__ float4 sKW[512];      // [256][8] as float4 pairs
  __shared__ float sPL[32 * 64];   // [32 points][8 n][8 j] partial logits

  const int tid = threadIdx.x;
  if (tid < 128) sW1[tid] = w1[tid];
  if (tid < 64) sB1[tid] = b1[tid];
  for (int i = tid; i < 512; i += 256) sW2[i] = ((const float4*)w2)[i];
  for (int i = tid; i < 512; i += 256) sKW[i] = ((const float4*)kw)[i];
  if (tid < 32) {
    sB2[tid] = b2[tid];
    sLNG[tid] = lng[tid];
    sLNB[tid] = lnb[tid];
  }
  if (tid < 8) sKB[tid] = kb[tid];
  __syncthreads();

  const int gid = blockIdx.x * 256 + tid;
  const int t = gid >> 3;
  const int n = gid & 7;
  const int si = g_idx[gid];
  const float r0 = cs[si] - cg[t];
  const float r1 = cs[S_SRC + si] - cg[T_GRID + t];

  float pe[32];
#pragma unroll
  for (int d = 0; d < 32; d++) pe[d] = sB2[d];

#pragma unroll 2
  for (int j = 0; j < 64; j++) {
    float h = fmaf(r1, sW1[64 + j], fmaf(r0, sW1[j], sB1[j]));
    float z = 0.7978845608028654f * fmaf(0.044715f, h * h * h, h);  // sqrt(2/pi)
    float g = 0.5f * h * (1.0f + tanhf(z));
#pragma unroll
    for (int q = 0; q < 8; q++) {
      float4 wv = sW2[j * 8 + q];
      pe[q * 4 + 0] = fmaf(g, wv.x, pe[q * 4 + 0]);
      pe[q * 4 + 1] = fmaf(g, wv.y, pe[q * 4 + 1]);
      pe[q * 4 + 2] = fmaf(g, wv.z, pe[q * 4 + 2]);
      pe[q * 4 + 3] = fmaf(g, wv.w, pe[q * 4 + 3]);
    }
  }

  // LayerNorm over 32
  float mu = 0.f;
#pragma unroll
  for (int d = 0; d < 32; d++) mu += pe[d];
  mu *= (1.0f / 32.0f);
  float var = 0.f;
#pragma unroll
  for (int d = 0; d < 32; d++) {
    float c = pe[d] - mu;
    var = fmaf(c, c, var);
  }
  var *= (1.0f / 32.0f);
  const float rstd = rsqrtf(var + 1e-5f);

  // Partial logits for this neighbor n
  float pl[8];
#pragma unroll
  for (int q = 0; q < 8; q++) pl[q] = 0.f;
#pragma unroll 4
  for (int d = 0; d < 32; d++) {
    float kf = fmaf((pe[d] - mu) * rstd, sLNG[d], sLNB[d]);
    float4 a = sKW[(n * 32 + d) * 2 + 0];
    float4 bq = sKW[(n * 32 + d) * 2 + 1];
    pl[0] = fmaf(kf, a.x, pl[0]);
    pl[1] = fmaf(kf, a.y, pl[1]);
    pl[2] = fmaf(kf, a.z, pl[2]);
    pl[3] = fmaf(kf, a.w, pl[3]);
    pl[4] = fmaf(kf, bq.x, pl[4]);
    pl[5] = fmaf(kf, bq.y, pl[5]);
    pl[6] = fmaf(kf, bq.z, pl[6]);
    pl[7] = fmaf(kf, bq.w, pl[7]);
  }
  const int lt = tid >> 3;
#pragma unroll
  for (int q = 0; q < 8; q++) sPL[lt * 64 + n * 8 + q] = pl[q];
  __syncthreads();

  // Phase 2: thread (lt2, jj) reduces over n, softmax across jj within 8-lane group
  const int lt2 = tid >> 3;
  const int jj = tid & 7;
  float lg = sKB[jj];
#pragma unroll
  for (int n2 = 0; n2 < 8; n2++) lg += sPL[lt2 * 64 + n2 * 8 + jj];
  float mx = lg;
#pragma unroll
  for (int off = 4; off > 0; off >>= 1)
    mx = fmaxf(mx, __shfl_xor_sync(0xffffffffu, mx, off));
  float e = expf(lg - mx);
  float ssum = e;
#pragma unroll
  for (int off = 4; off > 0; off >>= 1)
    ssum += __shfl_xor_sync(0xffffffffu, ssum, off);
  g_w[(blockIdx.x * 32 + lt2) * 8 + jj] = e / ssum;
}

// ---------------------------------------------------------------------------
// Kernel 3: xg[b,t,:] = sum_n w[t,n] * x[b, idx[t,n], :]   (stored (B,T,E))
// ---------------------------------------------------------------------------
__global__ __launch_bounds__(256) void xg_kernel(const float* __restrict__ x) {
  const int gid = blockIdx.x * 256 + threadIdx.x;  // 16384 = B*T
  const int b = gid >> 12;
  const int t = gid & 4095;
  float4 a0 = {0, 0, 0, 0}, a1 = a0, a2 = a0, a3 = a0;
#pragma unroll
  for (int nn = 0; nn < NHBR; nn++) {
    const int s = g_idx[t * NHBR + nn];
    const float w = g_w[t * NHBR + nn];
    const float4* xp = (const float4*)(x + (size_t)(b * S_SRC + s) * EDIM);
    fma4(a0, w, xp[0]);
    fma4(a1, w, xp[1]);
    fma4(a2, w, xp[2]);
    fma4(a3, w, xp[3]);
  }
  float4* op = (float4*)(g_xg + (size_t)gid * EDIM);
  op[0] = a0;
  op[1] = a1;
  op[2] = a2;
  op[3] = a3;
}

// ---------------------------------------------------------------------------
// Kernel 4: gaussian-window resampling onto targets. Thread per (b, n).
// grid[b,e,ix,iy] == g_xg[b, ix*64+iy, e]  (no transpose materialized)
// ---------------------------------------------------------------------------
__global__ __launch_bounds__(256) void interp_kernel(
    const float* __restrict__ ct, float* __restrict__ out) {
  const int gid = blockIdx.x * 256 + threadIdx.x;  // 32768 = B*N
  const int b = gid >> 13;
  const float cy = ct[gid * 2 + 0];  // -> posy
  const float cx = ct[gid * 2 + 1];  // -> posx
  const float posx = cx * 63.0f;
  const float posy = cy * 63.0f;
  const float rpx = rintf(posx);
  const float rpy = rintf(posy);

  float wx[5], wy[5];
  const float step = -5.0f / 89.0f;  // linspace(2.5,-2.5,90) step
#pragma unroll
  for (int i = 0; i < 5; i++) {
    float ax = 0.f, ay = 0.f;
#pragma unroll
    for (int k = 0; k < 18; k++) {
      const int j = i * 18 + k;
      float off = fmaf((float)j, step, 2.5f);
      float px = fminf(fmaxf(rpx - off, 0.0f), 64.0f);
      float py = fminf(fmaxf(rpy - off, 0.0f), 64.0f);
      float tx = (px - posx) * 2.0f;  // /SIG with SIG=0.5
      float ty = (py - posy) * 2.0f;
      ax += __expf(-0.5f * tx * tx);
      ay += __expf(-0.5f * ty * ty);
    }
    wx[i] = ax;
    wy[i] = ay;
  }
  const float sx = wx[0] + wx[1] + wx[2] + wx[3] + wx[4];
  const float sy = wy[0] + wy[1] + wy[2] + wy[3] + wy[4];
  const float inv = 1.0f / (sx * sy);

  int ixi[5], iyi[5];
  const int irpx = (int)rpx;
  const int irpy = (int)rpy;
#pragma unroll
  for (int k = 0; k < 5; k++) {
    ixi[k] = min(max(irpx + 2 - k, 0), 63);
    iyi[k] = min(max(irpy + 2 - k, 0), 63);
  }

  float4 a0 = {0, 0, 0, 0}, a1 = a0, a2 = a0, a3 = a0;
  const float* gbase = g_xg + (size_t)b * (T_GRID * EDIM);
#pragma unroll
  for (int kx = 0; kx < 5; kx++) {
    const int rowbase = ixi[kx] << 6;
    const float wxk = wx[kx] * inv;
#pragma unroll
    for (int ky = 0; ky < 5; ky++) {
      const float wc = wxk * wy[ky];
      const float4* gp = (const float4*)(gbase + (size_t)(rowbase + iyi[ky]) * EDIM);
      float4 v0 = gp[0], v1 = gp[1], v2 = gp[2], v3 = gp[3];
      fma4(a0, wc, v0);
      fma4(a1, wc, v1);
      fma4(a2, wc, v2);
      fma4(a3, wc, v3);
    }
  }
  float4* op = (float4*)(out + (size_t)gid * EDIM);
  op[0] = a0;
  op[1] = a1;
  op[2] = a2;
  op[3] = a3;
}

// ---------------------------------------------------------------------------
extern "C" void kernel_launch(void* const* d_in, const int* in_sizes, int n_in,
                              void* d_out, int out_size) {
  const float* x   = (const float*)d_in[0];
  const float* cs  = (const float*)d_in[1];
  const float* cg  = (const float*)d_in[2];
  const float* ct  = (const float*)d_in[3];
  const float* w1  = (const float*)d_in[4];
  const float* b1  = (const float*)d_in[5];
  const float* w2  = (const float*)d_in[6];
  const float* b2  = (const float*)d_in[7];
  const float* lng = (const float*)d_in[8];
  const float* lnb = (const float*)d_in[9];
  const float* kw  = (const float*)d_in[10];
  const float* kb  = (const float*)d_in[11];
  float* out = (float*)d_out;

  topk_kernel<<<512, 256>>>(cs, cg);
  weights_kernel<<<128, 256>>>(cs, cg, w1, b1, w2, b2, lng, lnb, kw, kb);
  xg_kernel<<<64, 256>>>(x);
  interp_kernel<<<128, 256>>>(ct, out);
}

// round 2
// speedup vs baseline: 2.4250x; 2.4250x over previous
#include <cuda_runtime.h>

#define S_SRC 16384
#define T_GRID 4096
#define NHBR 8
#define BATCH 4
#define EDIM 16
#define GBINS 64
#define NBINS (GBINS * GBINS)
#define CELL (1.0f / 64.0f)

// Scratch (static device globals — no allocation)
__device__ int    g_idx[T_GRID * NHBR];
__device__ float  g_w[T_GRID * NHBR];
__device__ float  g_xg[BATCH * T_GRID * EDIM];
__device__ int    g_cnt[NBINS];
__device__ int    g_start[NBINS];
__device__ int    g_pos[NBINS];
__device__ float2 g_bxy[S_SRC];
__device__ int    g_bidx[S_SRC];

__device__ __forceinline__ int clamp63(int v) { return min(max(v, 0), 63); }

// ---------------------------------------------------------------------------
// Binning pipeline: zero -> histogram -> scan -> scatter
// ---------------------------------------------------------------------------
__global__ void bin_zero() { g_cnt[blockIdx.x * 1024 + threadIdx.x] = 0; }

__global__ void bin_hist(const float* __restrict__ cs) {
  const int i = blockIdx.x * 1024 + threadIdx.x;
  const int bx = clamp63((int)(cs[i] * 64.0f));
  const int by = clamp63((int)(cs[S_SRC + i] * 64.0f));
  atomicAdd(&g_cnt[bx * GBINS + by], 1);
}

__global__ void bin_scan() {
  __shared__ int sh[1024];
  const int t = threadIdx.x;
  int c[4];
  int tot = 0;
#pragma unroll
  for (int i = 0; i < 4; i++) {
    c[i] = g_cnt[t * 4 + i];
    tot += c[i];
  }
  sh[t] = tot;
  __syncthreads();
  for (int off = 1; off < 1024; off <<= 1) {
    int v = (t >= off) ? sh[t - off] : 0;
    __syncthreads();
    sh[t] += v;
    __syncthreads();
  }
  int run = sh[t] - tot;  // exclusive
#pragma unroll
  for (int i = 0; i < 4; i++) {
    g_start[t * 4 + i] = run;
    g_pos[t * 4 + i] = run;
    run += c[i];
  }
}

__global__ void bin_scatter(const float* __restrict__ cs) {
  const int i = blockIdx.x * 1024 + threadIdx.x;
  const float x = cs[i];
  const float y = cs[S_SRC + i];
  const int b = clamp63((int)(x * 64.0f)) * GBINS + clamp63((int)(y * 64.0f));
  const int p = atomicAdd(&g_pos[b], 1);
  g_bxy[p] = make_float2(x, y);
  g_bidx[p] = i;
}

// ---------------------------------------------------------------------------
// Exact kNN (k=8) via expanding ring search over bins. One thread per point.
// Key = (float_bits(d2) << 32) | src_idx reproduces lax.top_k(-d2) order.
// ---------------------------------------------------------------------------
__device__ __forceinline__ void scan_bin(int b, float gx, float gy,
                                         unsigned long long best[8],
                                         float& worst) {
  const int s = g_start[b];
  const int e = s + g_cnt[b];
  for (int j = s; j < e; j++) {
    const float2 p = g_bxy[j];
    const float dx = gx - p.x;
    const float dy = gy - p.y;
    const float d2 = fmaf(dy, dy, dx * dx);
    if (d2 <= worst) {
      unsigned long long key =
          ((unsigned long long)__float_as_uint(d2) << 32) | (unsigned)g_bidx[j];
      if (key < best[7]) {
        best[7] = key;
#pragma unroll
        for (int k = 7; k > 0; k--) {
          unsigned long long lo = (best[k] < best[k - 1]) ? best[k] : best[k - 1];
          unsigned long long hi = (best[k] < best[k - 1]) ? best[k - 1] : best[k];
          best[k - 1] = lo;
          best[k] = hi;
        }
        worst = __uint_as_float((unsigned)(best[7] >> 32));
      }
    }
  }
}

__global__ __launch_bounds__(64) void knn_kernel(const float* __restrict__ cg) {
  const int t = blockIdx.x * 64 + threadIdx.x;
  const float gx = cg[t];
  const float gy = cg[T_GRID + t];
  const int hbx = clamp63((int)(gx * 64.0f));
  const int hby = clamp63((int)(gy * 64.0f));

  unsigned long long best[8];
#pragma unroll
  for (int i = 0; i < 8; i++) best[i] = 0x7F800000FFFFFFFFULL;
  float worst = __int_as_float(0x7F800000);

  for (int r = 0; r < GBINS; r++) {
    if (r >= 1) {
      const float dmin = (float)(r - 1) * CELL;
      if (dmin * dmin > worst) break;  // worst=inf until 8 found
    }
    const int x0 = max(hbx - r, 0), x1 = min(hbx + r, 63);
    for (int bx = x0; bx <= x1; bx++) {
      const int adx = abs(bx - hbx);
      if (adx == r) {  // full column
        const int y0 = max(hby - r, 0), y1 = min(hby + r, 63);
        for (int by = y0; by <= y1; by++)
          scan_bin(bx * GBINS + by, gx, gy, best, worst);
      } else {  // just the two horizontal edges
        if (hby - r >= 0) scan_bin(bx * GBINS + hby - r, gx, gy, best, worst);
        if (hby + r <= 63) scan_bin(bx * GBINS + hby + r, gx, gy, best, worst);
      }
    }
  }
#pragma unroll
  for (int k = 0; k < 8; k++)
    g_idx[t * NHBR + k] = (int)(best[k] & 0xFFFFFFFFu);
}

// ---------------------------------------------------------------------------
// Kernel 2: PE MLP (gelu-tanh) -> layernorm -> logits -> softmax
// ---------------------------------------------------------------------------
__device__ __forceinline__ void fma4(float4& a, float w, const float4 v) {
  a.x = fmaf(w, v.x, a.x);
  a.y = fmaf(w, v.y, a.y);
  a.z = fmaf(w, v.z, a.z);
  a.w = fmaf(w, v.w, a.w);
}

__global__ __launch_bounds__(256) void weights_kernel(
    const float* __restrict__ cs, const float* __restrict__ cg,
    const float* __restrict__ w1, const float* __restrict__ b1,
    const float* __restrict__ w2, const float* __restrict__ b2,
    const float* __restrict__ lng, const float* __restrict__ lnb,
    const float* __restrict__ kw, const float* __restrict__ kb) {
  __shared__ float sW1[128];
  __shared__ float sB1[64];
  __shared__ float4 sW2[512];
  __shared__ float sB2[32], sLNG[32], sLNB[32], sKB[8];
  __shared__ float4 sKW[512];
  __shared__ float sPL[32 * 64];

  const int tid = threadIdx.x;
  if (tid < 128) sW1[tid] = w1[tid];
  if (tid < 64) sB1[tid] = b1[tid];
  for (int i = tid; i < 512; i += 256) sW2[i] = ((const float4*)w2)[i];
  for (int i = tid; i < 512; i += 256) sKW[i] = ((const float4*)kw)[i];
  if (tid < 32) {
    sB2[tid] = b2[tid];
    sLNG[tid] = lng[tid];
    sLNB[tid] = lnb[tid];
  }
  if (tid < 8) sKB[tid] = kb[tid];
  __syncthreads();

  const int gid = blockIdx.x * 256 + tid;
  const int t = gid >> 3;
  const int n = gid & 7;
  const int si = g_idx[gid];
  const float r0 = cs[si] - cg[t];
  const float r1 = cs[S_SRC + si] - cg[T_GRID + t];

  float pe[32];
#pragma unroll
  for (int d = 0; d < 32; d++) pe[d] = sB2[d];

#pragma unroll 2
  for (int j = 0; j < 64; j++) {
    float h = fmaf(r1, sW1[64 + j], fmaf(r0, sW1[j], sB1[j]));
    float z = 0.7978845608028654f * fmaf(0.044715f, h * h * h, h);
    float g = 0.5f * h * (1.0f + tanhf(z));
#pragma unroll
    for (int q = 0; q < 8; q++) {
      float4 wv = sW2[j * 8 + q];
      pe[q * 4 + 0] = fmaf(g, wv.x, pe[q * 4 + 0]);
      pe[q * 4 + 1] = fmaf(g, wv.y, pe[q * 4 + 1]);
      pe[q * 4 + 2] = fmaf(g, wv.z, pe[q * 4 + 2]);
      pe[q * 4 + 3] = fmaf(g, wv.w, pe[q * 4 + 3]);
    }
  }

  float mu = 0.f;
#pragma unroll
  for (int d = 0; d < 32; d++) mu += pe[d];
  mu *= (1.0f / 32.0f);
  float var = 0.f;
#pragma unroll
  for (int d = 0; d < 32; d++) {
    float c = pe[d] - mu;
    var = fmaf(c, c, var);
  }
  var *= (1.0f / 32.0f);
  const float rstd = rsqrtf(var + 1e-5f);

  float pl[8];
#pragma unroll
  for (int q = 0; q < 8; q++) pl[q] = 0.f;
#pragma unroll 4
  for (int d = 0; d < 32; d++) {
    float kf = fmaf((pe[d] - mu) * rstd, sLNG[d], sLNB[d]);
    float4 a = sKW[(n * 32 + d) * 2 + 0];
    float4 bq = sKW[(n * 32 + d) * 2 + 1];
    pl[0] = fmaf(kf, a.x, pl[0]);
    pl[1] = fmaf(kf, a.y, pl[1]);
    pl[2] = fmaf(kf, a.z, pl[2]);
    pl[3] = fmaf(kf, a.w, pl[3]);
    pl[4] = fmaf(kf, bq.x, pl[4]);
    pl[5] = fmaf(kf, bq.y, pl[5]);
    pl[6] = fmaf(kf, bq.z, pl[6]);
    pl[7] = fmaf(kf, bq.w, pl[7]);
  }
  const int lt = tid >> 3;
#pragma unroll
  for (int q = 0; q < 8; q++) sPL[lt * 64 + n * 8 + q] = pl[q];
  __syncthreads();

  const int lt2 = tid >> 3;
  const int jj = tid & 7;
  float lg = sKB[jj];
#pragma unroll
  for (int n2 = 0; n2 < 8; n2++) lg += sPL[lt2 * 64 + n2 * 8 + jj];
  float mx = lg;
#pragma unroll
  for (int off = 4; off > 0; off >>= 1)
    mx = fmaxf(mx, __shfl_xor_sync(0xffffffffu, mx, off));
  float e = expf(lg - mx);
  float ssum = e;
#pragma unroll
  for (int off = 4; off > 0; off >>= 1)
    ssum += __shfl_xor_sync(0xffffffffu, ssum, off);
  g_w[(blockIdx.x * 32 + lt2) * 8 + jj] = e / ssum;
}

// ---------------------------------------------------------------------------
// Kernel 3: xg[b,t,:] = sum_n w[t,n] * x[b, idx[t,n], :]
// ---------------------------------------------------------------------------
__global__ __launch_bounds__(256) void xg_kernel(const float* __restrict__ x) {
  const int gid = blockIdx.x * 256 + threadIdx.x;
  const int b = gid >> 12;
  const int t = gid & 4095;
  float4 a0 = {0, 0, 0, 0}, a1 = a0, a2 = a0, a3 = a0;
#pragma unroll
  for (int nn = 0; nn < NHBR; nn++) {
    const int s = g_idx[t * NHBR + nn];
    const float w = g_w[t * NHBR + nn];
    const float4* xp = (const float4*)(x + (size_t)(b * S_SRC + s) * EDIM);
    fma4(a0, w, xp[0]);
    fma4(a1, w, xp[1]);
    fma4(a2, w, xp[2]);
    fma4(a3, w, xp[3]);
  }
  float4* op = (float4*)(g_xg + (size_t)gid * EDIM);
  op[0] = a0;
  op[1] = a1;
  op[2] = a2;
  op[3] = a3;
}

// ---------------------------------------------------------------------------
// Kernel 4: gaussian-window resampling. TWO threads per (b, n):
// even lane computes x-axis window, odd lane y-axis; exchange via shfl;
// each accumulates 8 of the 16 channels.
// ---------------------------------------------------------------------------
__global__ __launch_bounds__(256) void interp_kernel(
    const float* __restrict__ ct, float* __restrict__ out) {
  const int gid2 = blockIdx.x * 256 + threadIdx.x;  // 65536 = 2*B*N
  const int tgt = gid2 >> 1;
  const int half = gid2 & 1;
  const int b = tgt >> 13;
  const float cy = ct[tgt * 2 + 0];
  const float cx = ct[tgt * 2 + 1];
  const float posx = cx * 63.0f;
  const float posy = cy * 63.0f;
  const float rpx = rintf(posx);
  const float rpy = rintf(posy);

  const float pos = half ? posy : posx;
  const float rp = half ? rpy : rpx;

  float w[5];
  const float step = -5.0f / 89.0f;  // linspace(2.5,-2.5,90) step
#pragma unroll
  for (int i = 0; i < 5; i++) {
    float acc = 0.f;
#pragma unroll
    for (int k = 0; k < 18; k++) {
      const int j = i * 18 + k;
      float off = fmaf((float)j, step, 2.5f);
      float p = fminf(fmaxf(rp - off, 0.0f), 64.0f);
      float tt = (p - pos) * 2.0f;  // /SIG, SIG=0.5
      acc += __expf(-0.5f * tt * tt);
    }
    w[i] = acc;
  }
  float o[5];
#pragma unroll
  for (int i = 0; i < 5; i++) o[i] = __shfl_xor_sync(0xffffffffu, w[i], 1);

  float wx[5], wy[5];
#pragma unroll
  for (int i = 0; i < 5; i++) {
    wx[i] = half ? o[i] : w[i];
    wy[i] = half ? w[i] : o[i];
  }
  const float sx = wx[0] + wx[1] + wx[2] + wx[3] + wx[4];
  const float sy = wy[0] + wy[1] + wy[2] + wy[3] + wy[4];
  const float inv = 1.0f / (sx * sy);

  int ixi[5], iyi[5];
  const int irpx = (int)rpx;
  const int irpy = (int)rpy;
#pragma unroll
  for (int k = 0; k < 5; k++) {
    ixi[k] = min(max(irpx + 2 - k, 0), 63);
    iyi[k] = min(max(irpy + 2 - k, 0), 63);
  }

  float4 a0 = {0, 0, 0, 0}, a1 = a0;
  const float* gbase = g_xg + (size_t)b * (T_GRID * EDIM);
#pragma unroll
  for (int kx = 0; kx < 5; kx++) {
    const int rowbase = ixi[kx] << 6;
    const float wxk = wx[kx] * inv;
#pragma unroll
    for (int ky = 0; ky < 5; ky++) {
      const float wc = wxk * wy[ky];
      const float4* gp =
          (const float4*)(gbase + (size_t)(rowbase + iyi[ky]) * EDIM);
      fma4(a0, wc, gp[half * 2 + 0]);
      fma4(a1, wc, gp[half * 2 + 1]);
    }
  }
  float4* op = (float4*)(out + (size_t)tgt * EDIM);
  op[half * 2 + 0] = a0;
  op[half * 2 + 1] = a1;
}

// ---------------------------------------------------------------------------
extern "C" void kernel_launch(void* const* d_in, const int* in_sizes, int n_in,
                              void* d_out, int out_size) {
  const float* x   = (const float*)d_in[0];
  const float* cs  = (const float*)d_in[1];
  const float* cg  = (const float*)d_in[2];
  const float* ct  = (const float*)d_in[3];
  const float* w1  = (const float*)d_in[4];
  const float* b1  = (const float*)d_in[5];
  const float* w2  = (const float*)d_in[6];
  const float* b2  = (const float*)d_in[7];
  const float* lng = (const float*)d_in[8];
  const float* lnb = (const float*)d_in[9];
  const float* kw  = (const float*)d_in[10];
  const float* kb  = (const float*)d_in[11];
  float* out = (float*)d_out;

  bin_zero<<<4, 1024>>>();
  bin_hist<<<16, 1024>>>(cs);
  bin_scan<<<1, 1024>>>();
  bin_scatter<<<16, 1024>>>(cs);
  knn_kernel<<<64, 64>>>(cg);
  weights_kernel<<<128, 256>>>(cs, cg, w1, b1, w2, b2, lng, lnb, kw, kb);
  xg_kernel<<<64, 256>>>(x);
  interp_kernel<<<256, 256>>>(ct, out);
}

// round 3
// speedup vs baseline: 4.1475x; 1.7103x over previous
#include <cuda_runtime.h>

#define S_SRC 16384
#define T_GRID 4096
#define NHBR 8
#define BATCH 4
#define EDIM 16
#define GBINS 32
#define NBINS (GBINS * GBINS)
#define CELL (1.0f / 32.0f)

// Scratch (static device globals — no allocation)
__device__ int    g_idx[T_GRID * NHBR];
__device__ float  g_xg[BATCH * T_GRID * EDIM];
__device__ int    g_cnt[NBINS];
__device__ int    g_start[NBINS];
__device__ int    g_pos[NBINS];
__device__ float2 g_bxy[S_SRC];
__device__ int    g_bidx[S_SRC];

__device__ __forceinline__ int clampb(int v) { return min(max(v, 0), GBINS - 1); }

// ---------------------------------------------------------------------------
// Binning pipeline: zero -> histogram -> scan -> scatter (1024 bins)
// ---------------------------------------------------------------------------
__global__ void bin_zero() { g_cnt[threadIdx.x] = 0; }

__global__ void bin_hist(const float* __restrict__ cs) {
  const int i = blockIdx.x * 256 + threadIdx.x;
  const int bx = clampb((int)(cs[i] * (float)GBINS));
  const int by = clampb((int)(cs[S_SRC + i] * (float)GBINS));
  atomicAdd(&g_cnt[bx * GBINS + by], 1);
}

__global__ void bin_scan() {
  __shared__ int sh[NBINS];
  const int t = threadIdx.x;
  const int c = g_cnt[t];
  sh[t] = c;
  __syncthreads();
  for (int off = 1; off < NBINS; off <<= 1) {
    int v = (t >= off) ? sh[t - off] : 0;
    __syncthreads();
    sh[t] += v;
    __syncthreads();
  }
  const int excl = sh[t] - c;
  g_start[t] = excl;
  g_pos[t] = excl;
}

__global__ void bin_scatter(const float* __restrict__ cs) {
  const int i = blockIdx.x * 256 + threadIdx.x;
  const float x = cs[i];
  const float y = cs[S_SRC + i];
  const int b = clampb((int)(x * (float)GBINS)) * GBINS +
                clampb((int)(y * (float)GBINS));
  const int p = atomicAdd(&g_pos[b], 1);
  g_bxy[p] = make_float2(x, y);
  g_bidx[p] = i;
}

// ---------------------------------------------------------------------------
// Exact kNN (k=8): 8 lanes per grid point. Lane-local sorted top-8 +
// 8-round segment-shfl extraction merge. Key=(f32bits(d2)<<32)|idx matches
// lax.top_k(-d2) ordering incl. tie-break by lower index.
// ---------------------------------------------------------------------------
__device__ __forceinline__ void scan_bin8(int b, int l, float gx, float gy,
                                          unsigned long long best[8],
                                          float& worst) {
  const int s = g_start[b];
  const int e = s + g_cnt[b];
  for (int j = s + l; j < e; j += 8) {
    const float2 p = g_bxy[j];
    const float dx = gx - p.x;
    const float dy = gy - p.y;
    const float d2 = fmaf(dy, dy, dx * dx);
    if (d2 <= worst) {
      unsigned long long key =
          ((unsigned long long)__float_as_uint(d2) << 32) | (unsigned)g_bidx[j];
      if (key < best[7]) {
        best[7] = key;
#pragma unroll
        for (int k = 7; k > 0; k--) {
          unsigned long long lo = (best[k] < best[k - 1]) ? best[k] : best[k - 1];
          unsigned long long hi = (best[k] < best[k - 1]) ? best[k - 1] : best[k];
          best[k - 1] = lo;
          best[k] = hi;
        }
        worst = __uint_as_float((unsigned)(best[7] >> 32));
      }
    }
  }
}

// Non-destructive 8-way merge: lane k receives k-th smallest in `mine`;
// returns the 8th smallest (uniform across the 8-lane segment).
__device__ __forceinline__ unsigned long long merge8(
    const unsigned long long best[8], int l, unsigned gmask,
    unsigned long long& mine) {
  unsigned long long cand = best[0];
  int p = 0;
  unsigned long long m = 0;
#pragma unroll
  for (int k = 0; k < 8; k++) {
    m = cand;
#pragma unroll
    for (int off = 4; off > 0; off >>= 1) {
      unsigned long long o = __shfl_xor_sync(gmask, m, off, 8);
      m = (o < m) ? o : m;
    }
    if (l == k) mine = m;
    if (cand == m) {
      p++;
      cand = (p < 8) ? best[p] : 0xFFFFFFFFFFFFFFFFULL;
    }
  }
  return m;
}

__global__ __launch_bounds__(256) void knn_kernel(const float* __restrict__ cg) {
  const int tid = threadIdx.x;
  const int t = blockIdx.x * 32 + (tid >> 3);
  const int l = tid & 7;
  const unsigned gmask = 0xFFu << ((tid & 31) & 24);

  const float gx = cg[t];
  const float gy = cg[T_GRID + t];
  const int hbx = clampb((int)(gx * (float)GBINS));
  const int hby = clampb((int)(gy * (float)GBINS));

  unsigned long long best[8];
#pragma unroll
  for (int i = 0; i < 8; i++) best[i] = 0x7F800000FFFFFFFFULL;
  float worst = __int_as_float(0x7F800000);

  // Rings 0+1 together: 3x3 neighborhood (clamped)
  {
    const int x0 = max(hbx - 1, 0), x1 = min(hbx + 1, GBINS - 1);
    const int y0 = max(hby - 1, 0), y1 = min(hby + 1, GBINS - 1);
    for (int bx = x0; bx <= x1; bx++)
      for (int by = y0; by <= y1; by++)
        scan_bin8(bx * GBINS + by, l, gx, gy, best, worst);
  }

  unsigned long long mine;
  unsigned long long m8 = merge8(best, l, gmask, mine);
  float gw = __uint_as_float((unsigned)(m8 >> 32));

  // Rare continuation: expand rings until (completed_r * CELL)^2 > gw
  for (int r = 2; r < GBINS; r++) {
    const float dmin = (float)(r - 1) * CELL;
    if (dmin * dmin > gw) break;
    const int x0 = max(hbx - r, 0), x1 = min(hbx + r, GBINS - 1);
    for (int bx = x0; bx <= x1; bx++) {
      if (abs(bx - hbx) == r) {
        const int y0 = max(hby - r, 0), y1 = min(hby + r, GBINS - 1);
        for (int by = y0; by <= y1; by++)
          scan_bin8(bx * GBINS + by, l, gx, gy, best, worst);
      } else {
        if (hby - r >= 0) scan_bin8(bx * GBINS + hby - r, l, gx, gy, best, worst);
        if (hby + r <= GBINS - 1)
          scan_bin8(bx * GBINS + hby + r, l, gx, gy, best, worst);
      }
    }
    m8 = merge8(best, l, gmask, mine);
    gw = __uint_as_float((unsigned)(m8 >> 32));
  }

  g_idx[t * NHBR + l] = (int)(mine & 0xFFFFFFFFu);
}

// ---------------------------------------------------------------------------
// Kernel 2: PE MLP (gelu via sigmoid) -> LN -> logits -> softmax -> xg gather
// Block = 256 threads = 32 grid points.
// ---------------------------------------------------------------------------
__device__ __forceinline__ void fma4(float4& a, float w, const float4 v) {
  a.x = fmaf(w, v.x, a.x);
  a.y = fmaf(w, v.y, a.y);
  a.z = fmaf(w, v.z, a.z);
  a.w = fmaf(w, v.w, a.w);
}

__global__ __launch_bounds__(256) void weights_xg_kernel(
    const float* __restrict__ x,
    const float* __restrict__ cs, const float* __restrict__ cg,
    const float* __restrict__ w1, const float* __restrict__ b1,
    const float* __restrict__ w2, const float* __restrict__ b2,
    const float* __restrict__ lng, const float* __restrict__ lnb,
    const float* __restrict__ kw, const float* __restrict__ kb) {
  __shared__ float sW1[128];
  __shared__ float sB1[64];
  __shared__ float4 sW2[512];
  __shared__ float sB2[32], sLNG[32], sLNB[32], sKB[8];
  __shared__ float4 sKW[512];
  __shared__ float sPL[32 * 64];
  __shared__ int sIDX[256];
  __shared__ float sWgt[256];

  const int tid = threadIdx.x;
  if (tid < 128) sW1[tid] = w1[tid];
  if (tid < 64) sB1[tid] = b1[tid];
  for (int i = tid; i < 512; i += 256) sW2[i] = ((const float4*)w2)[i];
  for (int i = tid; i < 512; i += 256) sKW[i] = ((const float4*)kw)[i];
  if (tid < 32) {
    sB2[tid] = b2[tid];
    sLNG[tid] = lng[tid];
    sLNB[tid] = lnb[tid];
  }
  if (tid < 8) sKB[tid] = kb[tid];
  __syncthreads();

  const int gid = blockIdx.x * 256 + tid;
  const int t = gid >> 3;
  const int n = gid & 7;
  const int si = g_idx[gid];
  sIDX[tid] = si;
  const float r0 = cs[si] - cg[t];
  const float r1 = cs[S_SRC + si] - cg[T_GRID + t];

  float pe[32];
#pragma unroll
  for (int d = 0; d < 32; d++) pe[d] = sB2[d];

#pragma unroll 2
  for (int j = 0; j < 64; j++) {
    float h = fmaf(r1, sW1[64 + j], fmaf(r0, sW1[j], sB1[j]));
    float z = 0.7978845608028654f * fmaf(0.044715f, h * h * h, h);
    // gelu_tanh(h) = h * sigmoid(2z)
    float g = h * __fdividef(1.0f, 1.0f + __expf(-2.0f * z));
#pragma unroll
    for (int q = 0; q < 8; q++) {
      float4 wv = sW2[j * 8 + q];
      pe[q * 4 + 0] = fmaf(g, wv.x, pe[q * 4 + 0]);
      pe[q * 4 + 1] = fmaf(g, wv.y, pe[q * 4 + 1]);
      pe[q * 4 + 2] = fmaf(g, wv.z, pe[q * 4 + 2]);
      pe[q * 4 + 3] = fmaf(g, wv.w, pe[q * 4 + 3]);
    }
  }

  float mu = 0.f;
#pragma unroll
  for (int d = 0; d < 32; d++) mu += pe[d];
  mu *= (1.0f / 32.0f);
  float var = 0.f;
#pragma unroll
  for (int d = 0; d < 32; d++) {
    float c = pe[d] - mu;
    var = fmaf(c, c, var);
  }
  var *= (1.0f / 32.0f);
  const float rstd = rsqrtf(var + 1e-5f);

  float pl[8];
#pragma unroll
  for (int q = 0; q < 8; q++) pl[q] = 0.f;
#pragma unroll 4
  for (int d = 0; d < 32; d++) {
    float kf = fmaf((pe[d] - mu) * rstd, sLNG[d], sLNB[d]);
    float4 a = sKW[(n * 32 + d) * 2 + 0];
    float4 bq = sKW[(n * 32 + d) * 2 + 1];
    pl[0] = fmaf(kf, a.x, pl[0]);
    pl[1] = fmaf(kf, a.y, pl[1]);
    pl[2] = fmaf(kf, a.z, pl[2]);
    pl[3] = fmaf(kf, a.w, pl[3]);
    pl[4] = fmaf(kf, bq.x, pl[4]);
    pl[5] = fmaf(kf, bq.y, pl[5]);
    pl[6] = fmaf(kf, bq.z, pl[6]);
    pl[7] = fmaf(kf, bq.w, pl[7]);
  }
  const int lt = tid >> 3;
#pragma unroll
  for (int q = 0; q < 8; q++) sPL[lt * 64 + n * 8 + q] = pl[q];
  __syncthreads();

  // softmax: thread (lt, jj) reduces over n
  const int jj = tid & 7;
  float lg = sKB[jj];
#pragma unroll
  for (int n2 = 0; n2 < 8; n2++) lg += sPL[lt * 64 + n2 * 8 + jj];
  float mx = lg;
#pragma unroll
  for (int off = 4; off > 0; off >>= 1)
    mx = fmaxf(mx, __shfl_xor_sync(0xffffffffu, mx, off));
  float e = __expf(lg - mx);
  float ssum = e;
#pragma unroll
  for (int off = 4; off > 0; off >>= 1)
    ssum += __shfl_xor_sync(0xffffffffu, ssum, off);
  sWgt[lt * 8 + jj] = e / ssum;
  __syncthreads();

  // xg phase: unit = (point, batch); 2 threads per unit, 8 channels each.
  const int unit = tid >> 1;
  const int half = tid & 1;
  const int pt = unit >> 2;
  const int b = unit & 3;
  const int tg = blockIdx.x * 32 + pt;
  float4 a0 = {0, 0, 0, 0}, a1 = a0;
#pragma unroll
  for (int nn = 0; nn < NHBR; nn++) {
    const int s = sIDX[pt * 8 + nn];
    const float w = sWgt[pt * 8 + nn];
    const float4* xp =
        (const float4*)(x + (size_t)(b * S_SRC + s) * EDIM + half * 8);
    fma4(a0, w, xp[0]);
    fma4(a1, w, xp[1]);
  }
  float4* op = (float4*)(g_xg + (size_t)((b << 12) + tg) * EDIM + half * 8);
  op[0] = a0;
  op[1] = a1;
}

// ---------------------------------------------------------------------------
// Kernel 4: gaussian-window resampling. TWO threads per (b, n).
// ---------------------------------------------------------------------------
__global__ __launch_bounds__(256) void interp_kernel(
    const float* __restrict__ ct, float* __restrict__ out) {
  const int gid2 = blockIdx.x * 256 + threadIdx.x;  // 65536 = 2*B*N
  const int tgt = gid2 >> 1;
  const int half = gid2 & 1;
  const int b = tgt >> 13;
  const float cy = ct[tgt * 2 + 0];
  const float cx = ct[tgt * 2 + 1];
  const float posx = cx * 63.0f;
  const float posy = cy * 63.0f;
  const float rpx = rintf(posx);
  const float rpy = rintf(posy);

  const float pos = half ? posy : posx;
  const float rp = half ? rpy : rpx;

  float w[5];
  const float step = -5.0f / 89.0f;
#pragma unroll
  for (int i = 0; i < 5; i++) {
    float acc = 0.f;
#pragma unroll
    for (int k = 0; k < 18; k++) {
      const int j = i * 18 + k;
      float off = fmaf((float)j, step, 2.5f);
      float p = fminf(fmaxf(rp - off, 0.0f), 64.0f);
      float tt = (p - pos) * 2.0f;
      acc += __expf(-0.5f * tt * tt);
    }
    w[i] = acc;
  }
  float o[5];
#pragma unroll
  for (int i = 0; i < 5; i++) o[i] = __shfl_xor_sync(0xffffffffu, w[i], 1);

  float wx[5], wy[5];
#pragma unroll
  for (int i = 0; i < 5; i++) {
    wx[i] = half ? o[i] : w[i];
    wy[i] = half ? w[i] : o[i];
  }
  const float sx = wx[0] + wx[1] + wx[2] + wx[3] + wx[4];
  const float sy = wy[0] + wy[1] + wy[2] + wy[3] + wy[4];
  const float inv = 1.0f / (sx * sy);

  int ixi[5], iyi[5];
  const int irpx = (int)rpx;
  const int irpy = (int)rpy;
#pragma unroll
  for (int k = 0; k < 5; k++) {
    ixi[k] = min(max(irpx + 2 - k, 0), 63);
    iyi[k] = min(max(irpy + 2 - k, 0), 63);
  }

  float4 a0 = {0, 0, 0, 0}, a1 = a0;
  const float* gbase = g_xg + (size_t)b * (T_GRID * EDIM);
#pragma unroll
  for (int kx = 0; kx < 5; kx++) {
    const int rowbase = ixi[kx] << 6;
    const float wxk = wx[kx] * inv;
#pragma unroll
    for (int ky = 0; ky < 5; ky++) {
      const float wc = wxk * wy[ky];
      const float4* gp =
          (const float4*)(gbase + (size_t)(rowbase + iyi[ky]) * EDIM);
      fma4(a0, wc, gp[half * 2 + 0]);
      fma4(a1, wc, gp[half * 2 + 1]);
    }
  }
  float4* op = (float4*)(out + (size_t)tgt * EDIM);
  op[half * 2 + 0] = a0;
  op[half * 2 + 1] = a1;
}

// ---------------------------------------------------------------------------
extern "C" void kernel_launch(void* const* d_in, const int* in_sizes, int n_in,
                              void* d_out, int out_size) {
  const float* x   = (const float*)d_in[0];
  const float* cs  = (const float*)d_in[1];
  const float* cg  = (const float*)d_in[2];
  const float* ct  = (const float*)d_in[3];
  const float* w1  = (const float*)d_in[4];
  const float* b1  = (const float*)d_in[5];
  const float* w2  = (const float*)d_in[6];
  const float* b2  = (const float*)d_in[7];
  const float* lng = (const float*)d_in[8];
  const float* lnb = (const float*)d_in[9];
  const float* kw  = (const float*)d_in[10];
  const float* kb  = (const float*)d_in[11];
  float* out = (float*)d_out;

  bin_zero<<<1, 1024>>>();
  bin_hist<<<64, 256>>>(cs);
  bin_scan<<<1, 1024>>>();
  bin_scatter<<<64, 256>>>(cs);
  knn_kernel<<<128, 256>>>(cg);
  weights_xg_kernel<<<128, 256>>>(x, cs, cg, w1, b1, w2, b2, lng, lnb, kw, kb);
  interp_kernel<<<256, 256>>>(ct, out);
}

// round 4
// speedup vs baseline: 4.8020x; 1.1578x over previous
#include <cuda_runtime.h>

#define S_SRC 16384
#define T_GRID 4096
#define NHBR 8
#define BATCH 4
#define EDIM 16
#define GBINS 32
#define NBINS (GBINS * GBINS)
#define CELL (1.0f / 32.0f)
#define BCAP 96

// Scratch (static device globals — no allocation)
__device__ float  g_xg[BATCH * T_GRID * EDIM];
__device__ int    g_cnt[NBINS];
__device__ float2 g_bxy[NBINS * BCAP];
__device__ int    g_bidx[NBINS * BCAP];

__device__ __forceinline__ int clampb(int v) { return min(max(v, 0), GBINS - 1); }

// ---------------------------------------------------------------------------
// Binning: zero counts, then direct scatter into fixed-capacity bins.
// (Poisson(16) occupancy; BCAP=96 cannot overflow in practice. Order within a
// bin is nondeterministic but top-k uses a total order on (d2,idx) keys, so
// the final output is deterministic.)
// ---------------------------------------------------------------------------
__global__ void bin_zero() { g_cnt[threadIdx.x] = 0; }

__global__ __launch_bounds__(256) void bins_build(const float* __restrict__ cs) {
  const int i = blockIdx.x * 256 + threadIdx.x;
  const float x = cs[i];
  const float y = cs[S_SRC + i];
  const int b = clampb((int)(x * (float)GBINS)) * GBINS +
                clampb((int)(y * (float)GBINS));
  const int p = atomicAdd(&g_cnt[b], 1);
  if (p < BCAP) {
    g_bxy[b * BCAP + p] = make_float2(x, y);
    g_bidx[b * BCAP + p] = i;
  }
}

// ---------------------------------------------------------------------------
// Fused kernel: exact kNN (8 lanes/point) -> PE MLP -> LN -> logits ->
// softmax -> xg gather. Block = 256 threads = 32 grid points.
// Key = (f32bits(d2)<<32)|idx reproduces lax.top_k(-d2) order + tie-break.
// ---------------------------------------------------------------------------
__device__ __forceinline__ void scan_bin8(int b, int l, float gx, float gy,
                                          unsigned long long best[8],
                                          float& worst) {
  const int s = b * BCAP;
  const int e = s + min(g_cnt[b], BCAP);
  for (int j = s + l; j < e; j += 8) {
    const float2 p = g_bxy[j];
    const float dx = gx - p.x;
    const float dy = gy - p.y;
    const float d2 = fmaf(dy, dy, dx * dx);
    if (d2 <= worst) {
      unsigned long long key =
          ((unsigned long long)__float_as_uint(d2) << 32) | (unsigned)g_bidx[j];
      if (key < best[7]) {
        best[7] = key;
#pragma unroll
        for (int k = 7; k > 0; k--) {
          unsigned long long lo = (best[k] < best[k - 1]) ? best[k] : best[k - 1];
          unsigned long long hi = (best[k] < best[k - 1]) ? best[k - 1] : best[k];
          best[k - 1] = lo;
          best[k] = hi;
        }
        worst = __uint_as_float((unsigned)(best[7] >> 32));
      }
    }
  }
}

__device__ __forceinline__ unsigned long long merge8(
    const unsigned long long best[8], int l, unsigned gmask,
    unsigned long long& mine) {
  unsigned long long cand = best[0];
  int p = 0;
  unsigned long long m = 0;
#pragma unroll
  for (int k = 0; k < 8; k++) {
    m = cand;
#pragma unroll
    for (int off = 4; off > 0; off >>= 1) {
      unsigned long long o = __shfl_xor_sync(gmask, m, off, 8);
      m = (o < m) ? o : m;
    }
    if (l == k) mine = m;
    if (cand == m) {
      p++;
      cand = (p < 8) ? best[p] : 0xFFFFFFFFFFFFFFFFULL;
    }
  }
  return m;
}

__device__ __forceinline__ void fma4(float4& a, float w, const float4 v) {
  a.x = fmaf(w, v.x, a.x);
  a.y = fmaf(w, v.y, a.y);
  a.z = fmaf(w, v.z, a.z);
  a.w = fmaf(w, v.w, a.w);
}

__global__ __launch_bounds__(256) void fused_kernel(
    const float* __restrict__ x,
    const float* __restrict__ cs, const float* __restrict__ cg,
    const float* __restrict__ w1, const float* __restrict__ b1,
    const float* __restrict__ w2, const float* __restrict__ b2,
    const float* __restrict__ lng, const float* __restrict__ lnb,
    const float* __restrict__ kw, const float* __restrict__ kb) {
  __shared__ float sW1[128];
  __shared__ float sB1[64];
  __shared__ float4 sW2[512];
  __shared__ float sB2[32], sLNG[32], sLNB[32], sKB[8];
  __shared__ float4 sKW[512];
  __shared__ float sPL[32 * 64];
  __shared__ int sIDX[256];
  __shared__ float sWgt[256];

  const int tid = threadIdx.x;
  // Issue weight-table loads first; they complete under the knn phase.
  if (tid < 128) sW1[tid] = w1[tid];
  if (tid < 64) sB1[tid] = b1[tid];
  for (int i = tid; i < 512; i += 256) sW2[i] = ((const float4*)w2)[i];
  for (int i = tid; i < 512; i += 256) sKW[i] = ((const float4*)kw)[i];
  if (tid < 32) {
    sB2[tid] = b2[tid];
    sLNG[tid] = lng[tid];
    sLNB[tid] = lnb[tid];
  }
  if (tid < 8) sKB[tid] = kb[tid];

  // ---- Phase 1: kNN ----
  const int t = blockIdx.x * 32 + (tid >> 3);
  const int l = tid & 7;
  const unsigned gmask = 0xFFu << ((tid & 31) & 24);
  const float gx = cg[t];
  const float gy = cg[T_GRID + t];
  const int hbx = clampb((int)(gx * (float)GBINS));
  const int hby = clampb((int)(gy * (float)GBINS));

  unsigned long long best[8];
#pragma unroll
  for (int i = 0; i < 8; i++) best[i] = 0x7F800000FFFFFFFFULL;
  float worst = __int_as_float(0x7F800000);

  {
    const int x0 = max(hbx - 1, 0), x1 = min(hbx + 1, GBINS - 1);
    const int y0 = max(hby - 1, 0), y1 = min(hby + 1, GBINS - 1);
    for (int bx = x0; bx <= x1; bx++)
      for (int by = y0; by <= y1; by++)
        scan_bin8(bx * GBINS + by, l, gx, gy, best, worst);
  }

  unsigned long long mine;
  unsigned long long m8 = merge8(best, l, gmask, mine);
  float gw = __uint_as_float((unsigned)(m8 >> 32));

  for (int r = 2; r < GBINS; r++) {
    const float dmin = (float)(r - 1) * CELL;
    if (dmin * dmin > gw) break;
    const int x0 = max(hbx - r, 0), x1 = min(hbx + r, GBINS - 1);
    for (int bx = x0; bx <= x1; bx++) {
      if (abs(bx - hbx) == r) {
        const int y0 = max(hby - r, 0), y1 = min(hby + r, GBINS - 1);
        for (int by = y0; by <= y1; by++)
          scan_bin8(bx * GBINS + by, l, gx, gy, best, worst);
      } else {
        if (hby - r >= 0) scan_bin8(bx * GBINS + hby - r, l, gx, gy, best, worst);
        if (hby + r <= GBINS - 1)
          scan_bin8(bx * GBINS + hby + r, l, gx, gy, best, worst);
      }
    }
    m8 = merge8(best, l, gmask, mine);
    gw = __uint_as_float((unsigned)(m8 >> 32));
  }

  const int si = (int)(mine & 0xFFFFFFFFu);
  sIDX[tid] = si;

  // ---- Phase 2: PE MLP -> LN -> partial logits ----
  const float r0 = cs[si] - gx;
  const float r1 = cs[S_SRC + si] - gy;
  const int n = tid & 7;

  __syncthreads();  // weight tables ready

  float pe[32];
#pragma unroll
  for (int d = 0; d < 32; d++) pe[d] = sB2[d];

#pragma unroll 2
  for (int j = 0; j < 64; j++) {
    float h = fmaf(r1, sW1[64 + j], fmaf(r0, sW1[j], sB1[j]));
    float z = 0.7978845608028654f * fmaf(0.044715f, h * h * h, h);
    float g = h * __fdividef(1.0f, 1.0f + __expf(-2.0f * z));  // gelu_tanh
#pragma unroll
    for (int q = 0; q < 8; q++) {
      float4 wv = sW2[j * 8 + q];
      pe[q * 4 + 0] = fmaf(g, wv.x, pe[q * 4 + 0]);
      pe[q * 4 + 1] = fmaf(g, wv.y, pe[q * 4 + 1]);
      pe[q * 4 + 2] = fmaf(g, wv.z, pe[q * 4 + 2]);
      pe[q * 4 + 3] = fmaf(g, wv.w, pe[q * 4 + 3]);
    }
  }

  float mu = 0.f;
#pragma unroll
  for (int d = 0; d < 32; d++) mu += pe[d];
  mu *= (1.0f / 32.0f);
  float var = 0.f;
#pragma unroll
  for (int d = 0; d < 32; d++) {
    float c = pe[d] - mu;
    var = fmaf(c, c, var);
  }
  var *= (1.0f / 32.0f);
  const float rstd = rsqrtf(var + 1e-5f);

  float pl[8];
#pragma unroll
  for (int q = 0; q < 8; q++) pl[q] = 0.f;
#pragma unroll 4
  for (int d = 0; d < 32; d++) {
    float kf = fmaf((pe[d] - mu) * rstd, sLNG[d], sLNB[d]);
    float4 a = sKW[(n * 32 + d) * 2 + 0];
    float4 bq = sKW[(n * 32 + d) * 2 + 1];
    pl[0] = fmaf(kf, a.x, pl[0]);
    pl[1] = fmaf(kf, a.y, pl[1]);
    pl[2] = fmaf(kf, a.z, pl[2]);
    pl[3] = fmaf(kf, a.w, pl[3]);
    pl[4] = fmaf(kf, bq.x, pl[4]);
    pl[5] = fmaf(kf, bq.y, pl[5]);
    pl[6] = fmaf(kf, bq.z, pl[6]);
    pl[7] = fmaf(kf, bq.w, pl[7]);
  }
  const int lt = tid >> 3;
#pragma unroll
  for (int q = 0; q < 8; q++) sPL[lt * 64 + n * 8 + q] = pl[q];
  __syncthreads();

  // ---- Phase 3: softmax over neighbors ----
  const int jj = tid & 7;
  float lg = sKB[jj];
#pragma unroll
  for (int n2 = 0; n2 < 8; n2++) lg += sPL[lt * 64 + n2 * 8 + jj];
  float mx = lg;
#pragma unroll
  for (int off = 4; off > 0; off >>= 1)
    mx = fmaxf(mx, __shfl_xor_sync(0xffffffffu, mx, off));
  float e = __expf(lg - mx);
  float ssum = e;
#pragma unroll
  for (int off = 4; off > 0; off >>= 1)
    ssum += __shfl_xor_sync(0xffffffffu, ssum, off);
  sWgt[lt * 8 + jj] = e / ssum;
  __syncthreads();

  // ---- Phase 4: xg gather. unit = (point, batch); 2 threads x 8 channels ----
  const int unit = tid >> 1;
  const int half = tid & 1;
  const int pt = unit >> 2;
  const int b = unit & 3;
  const int tg = blockIdx.x * 32 + pt;
  float4 a0 = {0, 0, 0, 0}, a1 = a0;
#pragma unroll
  for (int nn = 0; nn < NHBR; nn++) {
    const int s = sIDX[pt * 8 + nn];
    const float w = sWgt[pt * 8 + nn];
    const float4* xp =
        (const float4*)(x + (size_t)(b * S_SRC + s) * EDIM + half * 8);
    fma4(a0, w, xp[0]);
    fma4(a1, w, xp[1]);
  }
  float4* op = (float4*)(g_xg + (size_t)((b << 12) + tg) * EDIM + half * 8);
  op[0] = a0;
  op[1] = a1;
}

// ---------------------------------------------------------------------------
// Kernel: gaussian-window resampling. TWO threads per (b, n).
// ---------------------------------------------------------------------------
__global__ __launch_bounds__(256) void interp_kernel(
    const float* __restrict__ ct, float* __restrict__ out) {
  const int gid2 = blockIdx.x * 256 + threadIdx.x;  // 65536 = 2*B*N
  const int tgt = gid2 >> 1;
  const int half = gid2 & 1;
  const int b = tgt >> 13;
  const float2 c2 = ((const float2*)ct)[tgt];
  const float posx = c2.y * 63.0f;
  const float posy = c2.x * 63.0f;
  const float rpx = rintf(posx);
  const float rpy = rintf(posy);

  const float pos = half ? posy : posx;
  const float rp = half ? rpy : rpx;

  float w[5];
  const float step = -5.0f / 89.0f;
#pragma unroll
  for (int i = 0; i < 5; i++) {
    float acc = 0.f;
#pragma unroll
    for (int k = 0; k < 18; k++) {
      const int j = i * 18 + k;
      float off = fmaf((float)j, step, 2.5f);
      float p = fminf(fmaxf(rp - off, 0.0f), 64.0f);
      float tt = (p - pos) * 2.0f;
      acc += __expf(-0.5f * tt * tt);
    }
    w[i] = acc;
  }
  float o[5];
#pragma unroll
  for (int i = 0; i < 5; i++) o[i] = __shfl_xor_sync(0xffffffffu, w[i], 1);

  float wx[5], wy[5];
#pragma unroll
  for (int i = 0; i < 5; i++) {
    wx[i] = half ? o[i] : w[i];
    wy[i] = half ? w[i] : o[i];
  }
  const float sx = wx[0] + wx[1] + wx[2] + wx[3] + wx[4];
  const float sy = wy[0] + wy[1] + wy[2] + wy[3] + wy[4];
  const float inv = 1.0f / (sx * sy);

  int ixi[5], iyi[5];
  const int irpx = (int)rpx;
  const int irpy = (int)rpy;
#pragma unroll
  for (int k = 0; k < 5; k++) {
    ixi[k] = min(max(irpx + 2 - k, 0), 63);
    iyi[k] = min(max(irpy + 2 - k, 0), 63);
  }

  float4 a0 = {0, 0, 0, 0}, a1 = a0;
  const float* gbase = g_xg + (size_t)b * (T_GRID * EDIM);
#pragma unroll
  for (int kx = 0; kx < 5; kx++) {
    const int rowbase = ixi[kx] << 6;
    const float wxk = wx[kx] * inv;
#pragma unroll
    for (int ky = 0; ky < 5; ky++) {
      const float wc = wxk * wy[ky];
      const float4* gp =
          (const float4*)(gbase + (size_t)(rowbase + iyi[ky]) * EDIM);
      fma4(a0, wc, gp[half * 2 + 0]);
      fma4(a1, wc, gp[half * 2 + 1]);
    }
  }
  float4* op = (float4*)(out + (size_t)tgt * EDIM);
  op[half * 2 + 0] = a0;
  op[half * 2 + 1] = a1;
}

// ---------------------------------------------------------------------------
extern "C" void kernel_launch(void* const* d_in, const int* in_sizes, int n_in,
                              void* d_out, int out_size) {
  const float* x   = (const float*)d_in[0];
  const float* cs  = (const float*)d_in[1];
  const float* cg  = (const float*)d_in[2];
  const float* ct  = (const float*)d_in[3];
  const float* w1  = (const float*)d_in[4];
  const float* b1  = (const float*)d_in[5];
  const float* w2  = (const float*)d_in[6];
  const float* b2  = (const float*)d_in[7];
  const float* lng = (const float*)d_in[8];
  const float* lnb = (const float*)d_in[9];
  const float* kw  = (const float*)d_in[10];
  const float* kb  = (const float*)d_in[11];
  float* out = (float*)d_out;

  bin_zero<<<1, 1024>>>();
  bins_build<<<64, 256>>>(cs);
  fused_kernel<<<128, 256>>>(x, cs, cg, w1, b1, w2, b2, lng, lnb, kw, kb);
  interp_kernel<<<256, 256>>>(ct, out);
}

// round 5
// speedup vs baseline: 4.8409x; 1.0081x over previous
#include <cuda_runtime.h>

#define S_SRC 16384
#define T_GRID 4096
#define NHBR 8
#define BATCH 4
#define EDIM 16
#define GBINS 32
#define NBINS (GBINS * GBINS)
#define CELL (1.0f / 32.0f)
#define BCAP 96

// Scratch (static device globals — no allocation). g_cnt is zero-initialized
// at module load and re-zeroed at the end of every launch (in interp_kernel),
// so each replay of the graph sees zeroed counts.
__device__ float  g_xg[BATCH * T_GRID * EDIM];
__device__ int    g_cnt[NBINS];
__device__ float2 g_bxy[NBINS * BCAP];
__device__ int    g_bidx[NBINS * BCAP];

__device__ __forceinline__ int clampb(int v) { return min(max(v, 0), GBINS - 1); }

// ---------------------------------------------------------------------------
// Binning: direct scatter into fixed-capacity bins (Poisson(16); BCAP=96
// cannot overflow in practice). Bin-internal order is nondeterministic but
// top-k uses a total order on (d2,idx) keys, so final output is deterministic.
// ---------------------------------------------------------------------------
__global__ __launch_bounds__(256) void bins_build(const float* __restrict__ cs) {
  const int i = blockIdx.x * 256 + threadIdx.x;
  const float x = cs[i];
  const float y = cs[S_SRC + i];
  const int b = clampb((int)(x * (float)GBINS)) * GBINS +
                clampb((int)(y * (float)GBINS));
  const int p = atomicAdd(&g_cnt[b], 1);
  if (p < BCAP) {
    g_bxy[b * BCAP + p] = make_float2(x, y);
    g_bidx[b * BCAP + p] = i;
  }
}

// ---------------------------------------------------------------------------
// Fused kernel: exact kNN (8 lanes/point) -> PE MLP -> LN -> logits ->
// softmax -> xg gather. Block = 256 threads = 32 grid points.
// Key = (f32bits(d2)<<32)|idx reproduces lax.top_k(-d2) order + tie-break.
// ---------------------------------------------------------------------------
__device__ __forceinline__ void scan_bin8(int b, int l, float gx, float gy,
                                          unsigned long long best[8],
                                          float& worst) {
  const int s = b * BCAP;
  const int e = s + min(g_cnt[b], BCAP);
  for (int j = s + l; j < e; j += 8) {
    const float2 p = g_bxy[j];
    const float dx = gx - p.x;
    const float dy = gy - p.y;
    const float d2 = fmaf(dy, dy, dx * dx);
    if (d2 <= worst) {
      unsigned long long key =
          ((unsigned long long)__float_as_uint(d2) << 32) | (unsigned)g_bidx[j];
      if (key < best[7]) {
        best[7] = key;
#pragma unroll
        for (int k = 7; k > 0; k--) {
          unsigned long long lo = (best[k] < best[k - 1]) ? best[k] : best[k - 1];
          unsigned long long hi = (best[k] < best[k - 1]) ? best[k - 1] : best[k];
          best[k - 1] = lo;
          best[k] = hi;
        }
        worst = __uint_as_float((unsigned)(best[7] >> 32));
      }
    }
  }
}

__device__ __forceinline__ unsigned long long merge8(
    const unsigned long long best[8], int l, unsigned gmask,
    unsigned long long& mine) {
  unsigned long long cand = best[0];
  int p = 0;
  unsigned long long m = 0;
#pragma unroll
  for (int k = 0; k < 8; k++) {
    m = cand;
#pragma unroll
    for (int off = 4; off > 0; off >>= 1) {
      unsigned long long o = __shfl_xor_sync(gmask, m, off, 8);
      m = (o < m) ? o : m;
    }
    if (l == k) mine = m;
    if (cand == m) {
      p++;
      cand = (p < 8) ? best[p] : 0xFFFFFFFFFFFFFFFFULL;
    }
  }
  return m;
}

__device__ __forceinline__ void fma4(float4& a, float w, const float4 v) {
  a.x = fmaf(w, v.x, a.x);
  a.y = fmaf(w, v.y, a.y);
  a.z = fmaf(w, v.z, a.z);
  a.w = fmaf(w, v.w, a.w);
}

__global__ __launch_bounds__(256) void fused_kernel(
    const float* __restrict__ x,
    const float* __restrict__ cs, const float* __restrict__ cg,
    const float* __restrict__ w1, const float* __restrict__ b1,
    const float* __restrict__ w2, const float* __restrict__ b2,
    const float* __restrict__ lng, const float* __restrict__ lnb,
    const float* __restrict__ kw, const float* __restrict__ kb) {
  __shared__ float sW1[128];
  __shared__ float sB1[64];
  __shared__ float4 sW2[512];
  __shared__ float sB2[32], sLNG[32], sLNB[32], sKB[8];
  __shared__ float4 sKW[512];
  __shared__ float sPL[32 * 64];
  __shared__ int sIDX[256];
  __shared__ float sWgt[256];

  const int tid = threadIdx.x;
  // Issue weight-table loads first; they complete under the knn phase.
  if (tid < 128) sW1[tid] = w1[tid];
  if (tid < 64) sB1[tid] = b1[tid];
  for (int i = tid; i < 512; i += 256) sW2[i] = ((const float4*)w2)[i];
  for (int i = tid; i < 512; i += 256) sKW[i] = ((const float4*)kw)[i];
  if (tid < 32) {
    sB2[tid] = b2[tid];
    sLNG[tid] = lng[tid];
    sLNB[tid] = lnb[tid];
  }
  if (tid < 8) sKB[tid] = kb[tid];

  // ---- Phase 1: kNN ----
  const int t = blockIdx.x * 32 + (tid >> 3);
  const int l = tid & 7;
  const unsigned gmask = 0xFFu << ((tid & 31) & 24);
  const float gx = cg[t];
  const float gy = cg[T_GRID + t];
  const int hbx = clampb((int)(gx * (float)GBINS));
  const int hby = clampb((int)(gy * (float)GBINS));

  unsigned long long best[8];
#pragma unroll
  for (int i = 0; i < 8; i++) best[i] = 0x7F800000FFFFFFFFULL;
  float worst = __int_as_float(0x7F800000);

  {
    const int x0 = max(hbx - 1, 0), x1 = min(hbx + 1, GBINS - 1);
    const int y0 = max(hby - 1, 0), y1 = min(hby + 1, GBINS - 1);
    for (int bx = x0; bx <= x1; bx++)
      for (int by = y0; by <= y1; by++)
        scan_bin8(bx * GBINS + by, l, gx, gy, best, worst);
  }

  unsigned long long mine;
  unsigned long long m8 = merge8(best, l, gmask, mine);
  float gw = __uint_as_float((unsigned)(m8 >> 32));

  for (int r = 2; r < GBINS; r++) {
    const float dmin = (float)(r - 1) * CELL;
    if (dmin * dmin > gw) break;
    const int x0 = max(hbx - r, 0), x1 = min(hbx + r, GBINS - 1);
    for (int bx = x0; bx <= x1; bx++) {
      if (abs(bx - hbx) == r) {
        const int y0 = max(hby - r, 0), y1 = min(hby + r, GBINS - 1);
        for (int by = y0; by <= y1; by++)
          scan_bin8(bx * GBINS + by, l, gx, gy, best, worst);
      } else {
        if (hby - r >= 0) scan_bin8(bx * GBINS + hby - r, l, gx, gy, best, worst);
        if (hby + r <= GBINS - 1)
          scan_bin8(bx * GBINS + hby + r, l, gx, gy, best, worst);
      }
    }
    m8 = merge8(best, l, gmask, mine);
    gw = __uint_as_float((unsigned)(m8 >> 32));
  }

  const int si = (int)(mine & 0xFFFFFFFFu);
  sIDX[tid] = si;

  // ---- Phase 2: PE MLP -> LN -> partial logits ----
  const float r0 = cs[si] - gx;
  const float r1 = cs[S_SRC + si] - gy;
  const int n = tid & 7;

  __syncthreads();  // weight tables ready

  float pe[32];
#pragma unroll
  for (int d = 0; d < 32; d++) pe[d] = sB2[d];

#pragma unroll 2
  for (int j = 0; j < 64; j++) {
    float h = fmaf(r1, sW1[64 + j], fmaf(r0, sW1[j], sB1[j]));
    float z = 0.7978845608028654f * fmaf(0.044715f, h * h * h, h);
    float g = h * __fdividef(1.0f, 1.0f + __expf(-2.0f * z));  // gelu_tanh
#pragma unroll
    for (int q = 0; q < 8; q++) {
      float4 wv = sW2[j * 8 + q];
      pe[q * 4 + 0] = fmaf(g, wv.x, pe[q * 4 + 0]);
      pe[q * 4 + 1] = fmaf(g, wv.y, pe[q * 4 + 1]);
      pe[q * 4 + 2] = fmaf(g, wv.z, pe[q * 4 + 2]);
      pe[q * 4 + 3] = fmaf(g, wv.w, pe[q * 4 + 3]);
    }
  }

  float mu = 0.f;
#pragma unroll
  for (int d = 0; d < 32; d++) mu += pe[d];
  mu *= (1.0f / 32.0f);
  float var = 0.f;
#pragma unroll
  for (int d = 0; d < 32; d++) {
    float c = pe[d] - mu;
    var = fmaf(c, c, var);
  }
  var *= (1.0f / 32.0f);
  const float rstd = rsqrtf(var + 1e-5f);

  float pl[8];
#pragma unroll
  for (int q = 0; q < 8; q++) pl[q] = 0.f;
#pragma unroll 4
  for (int d = 0; d < 32; d++) {
    float kf = fmaf((pe[d] - mu) * rstd, sLNG[d], sLNB[d]);
    float4 a = sKW[(n * 32 + d) * 2 + 0];
    float4 bq = sKW[(n * 32 + d) * 2 + 1];
    pl[0] = fmaf(kf, a.x, pl[0]);
    pl[1] = fmaf(kf, a.y, pl[1]);
    pl[2] = fmaf(kf, a.z, pl[2]);
    pl[3] = fmaf(kf, a.w, pl[3]);
    pl[4] = fmaf(kf, bq.x, pl[4]);
    pl[5] = fmaf(kf, bq.y, pl[5]);
    pl[6] = fmaf(kf, bq.z, pl[6]);
    pl[7] = fmaf(kf, bq.w, pl[7]);
  }
  const int lt = tid >> 3;
#pragma unroll
  for (int q = 0; q < 8; q++) sPL[lt * 64 + n * 8 + q] = pl[q];
  __syncthreads();

  // ---- Phase 3: softmax over neighbors ----
  const int jj = tid & 7;
  float lg = sKB[jj];
#pragma unroll
  for (int n2 = 0; n2 < 8; n2++) lg += sPL[lt * 64 + n2 * 8 + jj];
  float mx = lg;
#pragma unroll
  for (int off = 4; off > 0; off >>= 1)
    mx = fmaxf(mx, __shfl_xor_sync(0xffffffffu, mx, off));
  float e = __expf(lg - mx);
  float ssum = e;
#pragma unroll
  for (int off = 4; off > 0; off >>= 1)
    ssum += __shfl_xor_sync(0xffffffffu, ssum, off);
  sWgt[lt * 8 + jj] = e / ssum;
  __syncthreads();

  // ---- Phase 4: xg gather. unit = (point, batch); 2 threads x 8 channels ----
  const int unit = tid >> 1;
  const int half = tid & 1;
  const int pt = unit >> 2;
  const int b = unit & 3;
  const int tg = blockIdx.x * 32 + pt;
  float4 a0 = {0, 0, 0, 0}, a1 = a0;
#pragma unroll
  for (int nn = 0; nn < NHBR; nn++) {
    const int s = sIDX[pt * 8 + nn];
    const float w = sWgt[pt * 8 + nn];
    const float4* xp =
        (const float4*)(x + (size_t)(b * S_SRC + s) * EDIM + half * 8);
    fma4(a0, w, xp[0]);
    fma4(a1, w, xp[1]);
  }
  float4* op = (float4*)(g_xg + (size_t)((b << 12) + tg) * EDIM + half * 8);
  op[0] = a0;
  op[1] = a1;
}

// ---------------------------------------------------------------------------
// Gaussian-window resampling. TWO threads per (b, n): even lane = x axis,
// odd lane = y axis; exchange via shfl.
// Factorized weights: exp(-2(d-off_j)^2) = G * C_j * r^j with r=exp(-20d/89),
// C_j = exp(-2 off_j^2) (smem table). G is a per-axis common factor that
// cancels in the normalization, so the common path needs ONE __expf.
// Clipped edges (irp<=2 or irp>=62) get a correction loop: clipped terms all
// equal K = exp(-2*clamp_dist^2); true scale restored via G in that branch.
// Also zeroes g_cnt (block 0) for the next graph replay.
// ---------------------------------------------------------------------------
__global__ __launch_bounds__(256) void interp_kernel(
    const float* __restrict__ ct, float* __restrict__ out) {
  __shared__ float sC[90];
  {
    const int tt = threadIdx.x;
    if (tt < 90) {
      float off = fmaf((float)tt, -5.0f / 89.0f, 2.5f);
      sC[tt] = __expf(-2.0f * off * off);
    }
    if (blockIdx.x == 0) {
      for (int i = tt; i < NBINS; i += 256) g_cnt[i] = 0;
    }
  }
  __syncthreads();

  const int gid2 = blockIdx.x * 256 + threadIdx.x;  // 65536 = 2*B*N
  const int tgt = gid2 >> 1;
  const int half = gid2 & 1;
  const int b = tgt >> 13;
  const float2 c2 = ((const float2*)ct)[tgt];
  const float posx = c2.y * 63.0f;
  const float posy = c2.x * 63.0f;
  const float rpx = rintf(posx);
  const float rpy = rintf(posy);

  const float pos = half ? posy : posx;
  const float rp = half ? rpy : rpx;
  const float delta = rp - pos;  // in [-0.5, 0.5]
  const float lnr = -(20.0f / 89.0f) * delta;
  const float r = __expf(lnr);

  float S0 = 0.f, S1 = 0.f, S2 = 0.f, S3 = 0.f, S4 = 0.f;
  float rr = 1.0f;
#pragma unroll
  for (int k = 0; k < 18; k++) {
    S0 = fmaf(sC[k], rr, S0);
    S1 = fmaf(sC[18 + k], rr, S1);
    S2 = fmaf(sC[36 + k], rr, S2);
    S3 = fmaf(sC[54 + k], rr, S3);
    S4 = fmaf(sC[72 + k], rr, S4);
    rr *= r;
  }
  const float q = rr;  // r^18
  const float q2 = q * q;
  float w[5];
  w[0] = S0;
  w[1] = q * S1;
  w[2] = q2 * S2;
  w[3] = q2 * q * S3;
  w[4] = q2 * q2 * S4;

  const int irp = (int)rp;
  if (irp <= 2 || irp >= 62) {
    const float G = __expf(fmaf(-2.0f * delta, delta, 10.0f * delta));
#pragma unroll
    for (int i = 0; i < 5; i++) w[i] *= G;
    if (irp <= 2) {
      // terms j with off_j > rp are clipped to p=0
      const int j0 = (int)ceilf((2.5f - rp) * 17.8f);
      const float K = __expf(-2.0f * pos * pos);
      float rj = G;  // G * r^0
#pragma unroll
      for (int i = 0; i < 5; i++) {
        const int jlo = i * 18;
        const int jhi = min(j0, jlo + 18);
        float c = 0.f;
        for (int j = jlo; j < jhi; j++) {
          c += K - sC[j] * rj;
          rj *= r;
        }
        w[i] += c;
      }
    } else {
      // terms j with off_j < rp-64 are clipped to p=64
      const float d64 = 64.0f - pos;
      const float K = __expf(-2.0f * d64 * d64);
      const int jc = (int)floorf((66.5f - rp) * 17.8f) + 1;
      float rj = G * __expf(lnr * (float)jc);
#pragma unroll
      for (int i = 4; i >= 0; i--) {
        // iterate descending groups but ascending j overall: compute bounds
        (void)i;
      }
      {
        float rjj = rj;
#pragma unroll
        for (int i = 0; i < 5; i++) {
          const int jlo = max(jc, i * 18);
          const int jhi = (i + 1) * 18;
          float c = 0.f;
          for (int j = jlo; j < jhi; j++) {
            c += K - sC[j] * rjj;
            rjj *= r;
          }
          w[i] += c;
        }
      }
    }
  }

  float o[5];
#pragma unroll
  for (int i = 0; i < 5; i++) o[i] = __shfl_xor_sync(0xffffffffu, w[i], 1);

  float wx[5], wy[5];
#pragma unroll
  for (int i = 0; i < 5; i++) {
    wx[i] = half ? o[i] : w[i];
    wy[i] = half ? w[i] : o[i];
  }
  const float sx = wx[0] + wx[1] + wx[2] + wx[3] + wx[4];
  const float sy = wy[0] + wy[1] + wy[2] + wy[3] + wy[4];
  const float inv = 1.0f / (sx * sy);

  int ixi[5], iyi[5];
  const int irpx = (int)rpx;
  const int irpy = (int)rpy;
#pragma unroll
  for (int k = 0; k < 5; k++) {
    ixi[k] = min(max(irpx + 2 - k, 0), 63);
    iyi[k] = min(max(irpy + 2 - k, 0), 63);
  }

  float4 a0 = {0, 0, 0, 0}, a1 = a0;
  const float* gbase = g_xg + (size_t)b * (T_GRID * EDIM);
#pragma unroll
  for (int kx = 0; kx < 5; kx++) {
    const int rowbase = ixi[kx] << 6;
    const float wxk = wx[kx] * inv;
#pragma unroll
    for (int ky = 0; ky < 5; ky++) {
      const float wc = wxk * wy[ky];
      const float4* gp =
          (const float4*)(gbase + (size_t)(rowbase + iyi[ky]) * EDIM);
      fma4(a0, wc, gp[half * 2 + 0]);
      fma4(a1, wc, gp[half * 2 + 1]);
    }
  }
  float4* op = (float4*)(out + (size_t)tgt * EDIM);
  op[half * 2 + 0] = a0;
  op[half * 2 + 1] = a1;
}

// ---------------------------------------------------------------------------
extern "C" void kernel_launch(void* const* d_in, const int* in_sizes, int n_in,
                              void* d_out, int out_size) {
  const float* x   = (const float*)d_in[0];
  const float* cs  = (const float*)d_in[1];
  const float* cg  = (const float*)d_in[2];
  const float* ct  = (const float*)d_in[3];
  const float* w1  = (const float*)d_in[4];
  const float* b1  = (const float*)d_in[5];
  const float* w2  = (const float*)d_in[6];
  const float* b2  = (const float*)d_in[7];
  const float* lng = (const float*)d_in[8];
  const float* lnb = (const float*)d_in[9];
  const float* kw  = (const float*)d_in[10];
  const float* kb  = (const float*)d_in[11];
  float* out = (float*)d_out;

  bins_build<<<64, 256>>>(cs);
  fused_kernel<<<128, 256>>>(x, cs, cg, w1, b1, w2, b2, lng, lnb, kw, kb);
  interp_kernel<<<256, 256>>>(ct, out);
}